// round 3
// baseline (speedup 1.0000x reference)
#include <cuda_runtime.h>

// ---------------- problem constants ----------------
#define B 4
#define T_TOTAL 35968706LL          // sum of all 52 weight-tensor sizes
#define NV (T_TOTAL / 2)            // float2 count per row (T is even; NV is odd)

// ---------------- device scratch (no allocs allowed) ----------------
__device__ float g_c1[4 * 4  * 112 * 112];
__device__ float g_c2[4 * 8  * 56  * 56];
__device__ float g_c3[4 * 16 * 28  * 28];
__device__ float g_c4[4 * 32 * 14  * 14];
__device__ float g_c5[4 * 64 * 7   * 7];
__device__ float g_q[64];           // q[b][j], b*16+j

// ---------------- split-K conv: k=4, s=2, p=1 ----------------
// Block = 256 threads = OPT outputs x G partial channel-groups.
// Output counts all divide OPT exactly, so no bounds guard on outputs.
template<int CIN, int G, bool LRELU>
__global__ void __launch_bounds__(256)
conv_split(const float* __restrict__ x, const float* __restrict__ w,
           const float* __restrict__ bias, float* __restrict__ y,
           int Hin, int Win, int Cout, int Hout, int Wout)
{
    constexpr int OPT = 256 / G;      // outputs per block
    constexpr int CPG = CIN / G;      // channels per partial group
    const int tid = threadIdx.x;
    const int g   = tid / OPT;
    const int ol  = tid % OPT;

    long long oidx = (long long)blockIdx.x * OPT + ol;
    int ow = (int)(oidx % Wout); long long t = oidx / Wout;
    int oh = (int)(t % Hout);    t /= Hout;
    int co = (int)(t % Cout);
    int n  = (int)(t / Cout);

    const int ih0 = oh * 2 - 1, iw0 = ow * 2 - 1;
    const float* xn = x + ((long long)n * CIN + g * CPG) * Hin * Win;
    const float* wc = w + ((long long)co * CIN + g * CPG) * 16;

    float acc = 0.f;
    #pragma unroll
    for (int ci = 0; ci < CPG; ci++) {
        const float* xc = xn + ci * Hin * Win;
        const float* wk = wc + ci * 16;
        #pragma unroll
        for (int kh = 0; kh < 4; kh++) {
            int ih = ih0 + kh;
            if ((unsigned)ih >= (unsigned)Hin) continue;
            const float* xr = xc + ih * Win;
            #pragma unroll
            for (int kw = 0; kw < 4; kw++) {
                int iw = iw0 + kw;
                if ((unsigned)iw < (unsigned)Win)
                    acc = fmaf(xr[iw], wk[kh * 4 + kw], acc);
            }
        }
    }

    if (G == 1) {
        acc += bias[co];
        if (LRELU) acc = (acc >= 0.f) ? acc : 0.01f * acc;
        y[oidx] = acc;
    } else {
        __shared__ float s[256];
        s[tid] = acc;
        __syncthreads();
        if (g == 0) {
            float sum = acc;
            #pragma unroll
            for (int j = 1; j < G; j++) sum += s[j * OPT + ol];
            sum += bias[co];
            if (LRELU) sum = (sum >= 0.f) ? sum : 0.01f * sum;
            y[oidx] = sum;
        }
    }
}

// ---------------- head: pool -> fc1 -> fc2 -> VQ -> q, loss ----------------
__global__ void head_k(const float* __restrict__ conv5,
                       const float* __restrict__ fc1w, const float* __restrict__ fc1b,
                       const float* __restrict__ fc2w, const float* __restrict__ fc2b,
                       const float* __restrict__ emb,
                       float* __restrict__ loss_out)
{
    __shared__ float sx[4][64];
    __shared__ float sh[4][16];
    __shared__ float se[4][16];
    __shared__ int   sidx[4];
    __shared__ float sred[64];
    int tid = threadIdx.x;                 // blockDim.x == 256

    // adaptive avg pool over 7x7
    {
        int b = tid >> 6, c = tid & 63;
        const float* p = conv5 + (b * 64 + c) * 49;
        float s = 0.f;
        #pragma unroll
        for (int i = 0; i < 49; i++) s += p[i];
        sx[b][c] = s * (1.f / 49.f);
    }
    __syncthreads();

    // fc1 (64->16) + lrelu
    if (tid < 64) {
        int b = tid >> 4, j = tid & 15;
        float s = fc1b[j];
        #pragma unroll
        for (int k = 0; k < 64; k++) s += sx[b][k] * fc1w[j * 64 + k];
        sh[b][j] = (s >= 0.f) ? s : 0.01f * s;
    }
    __syncthreads();

    // fc2 (16->16)
    if (tid < 64) {
        int b = tid >> 4, j = tid & 15;
        float s = fc2b[j];
        #pragma unroll
        for (int k = 0; k < 16; k++) s += sh[b][k] * fc2w[j * 16 + k];
        se[b][j] = s;
    }
    __syncthreads();

    // VQ nearest-codebook (first-min semantics like jnp.argmin)
    if (tid < 4) {
        int b = tid;
        float ee = 0.f;
        #pragma unroll
        for (int j = 0; j < 16; j++) ee += se[b][j] * se[b][j];
        float best = __int_as_float(0x7f800000);   // +inf
        int bi = 0;
        for (int c = 0; c < 4; c++) {
            float s2 = 0.f, dot = 0.f;
            #pragma unroll
            for (int j = 0; j < 16; j++) {
                float w = emb[c * 16 + j];
                s2  += w * w;
                dot += w * se[b][j];
            }
            float d = ee + s2 - 2.f * dot;
            if (d < best) { best = d; bi = c; }
        }
        sidx[b] = bi;
    }
    __syncthreads();

    // q + loss = 1.25 * mean((q - e)^2)
    if (tid < 64) {
        int b = tid >> 4, j = tid & 15;
        float qv = emb[sidx[b] * 16 + j];
        g_q[tid] = qv;
        float diff = qv - se[b][j];
        sred[tid] = diff * diff;
    }
    __syncthreads();
    if (tid == 0) {
        float s = 0.f;
        for (int i = 0; i < 64; i++) s += sred[i];
        *loss_out = 1.25f * s * (1.f / 64.f);
    }
}

// ---------------- the big streaming GEMM: out = q @ W_all ----------------
// Each thread handles 2 consecutive float2 elements -> 32 independent LDG.64
// in flight per thread, fully coalesced 512B per warp per row stream.
__global__ void __launch_bounds__(256)
gemm_k(const float* __restrict__ W, float* __restrict__ out)
{
    __shared__ float sq[64];
    if (threadIdx.x < 64) sq[threadIdx.x] = g_q[threadIdx.x];
    __syncthreads();

    long long i0 = ((long long)blockIdx.x * blockDim.x + threadIdx.x) * 2;
    if (i0 >= NV) return;
    const bool has2 = (i0 + 1 < NV);

    const float2* __restrict__ W2 = (const float2*)W;
    float2 a0 = {0,0}, a1 = {0,0}, a2 = {0,0}, a3 = {0,0};
    float2 b0 = {0,0}, b1 = {0,0}, b2 = {0,0}, b3 = {0,0};

    #pragma unroll
    for (int k = 0; k < 16; k++) {
        const float2* p = &W2[(long long)k * NV + i0];
        float2 wA = __ldcs(p);
        float2 wB = has2 ? __ldcs(p + 1) : make_float2(0.f, 0.f);
        float q0 = sq[k], q1 = sq[16 + k], q2 = sq[32 + k], q3 = sq[48 + k];
        a0.x = fmaf(q0, wA.x, a0.x); a0.y = fmaf(q0, wA.y, a0.y);
        a1.x = fmaf(q1, wA.x, a1.x); a1.y = fmaf(q1, wA.y, a1.y);
        a2.x = fmaf(q2, wA.x, a2.x); a2.y = fmaf(q2, wA.y, a2.y);
        a3.x = fmaf(q3, wA.x, a3.x); a3.y = fmaf(q3, wA.y, a3.y);
        b0.x = fmaf(q0, wB.x, b0.x); b0.y = fmaf(q0, wB.y, b0.y);
        b1.x = fmaf(q1, wB.x, b1.x); b1.y = fmaf(q1, wB.y, b1.y);
        b2.x = fmaf(q2, wB.x, b2.x); b2.y = fmaf(q2, wB.y, b2.y);
        b3.x = fmaf(q3, wB.x, b3.x); b3.y = fmaf(q3, wB.y, b3.y);
    }

    float2* __restrict__ O2 = (float2*)out;
    __stcs(&O2[i0],              a0);
    __stcs(&O2[NV + i0],         a1);
    __stcs(&O2[2 * NV + i0],     a2);
    __stcs(&O2[3 * NV + i0],     a3);
    if (has2) {
        __stcs(&O2[i0 + 1],          b0);
        __stcs(&O2[NV + i0 + 1],     b1);
        __stcs(&O2[2 * NV + i0 + 1], b2);
        __stcs(&O2[3 * NV + i0 + 1], b3);
    }
}

// ---------------- launch ----------------
extern "C" void kernel_launch(void* const* d_in, const int* in_sizes, int n_in,
                              void* d_out, int out_size)
{
    const float* rgb   = (const float*)d_in[0];
    const float* cw1   = (const float*)d_in[1];
    const float* cb1   = (const float*)d_in[2];
    const float* cw2   = (const float*)d_in[3];
    const float* cb2   = (const float*)d_in[4];
    const float* cw3   = (const float*)d_in[5];
    const float* cb3   = (const float*)d_in[6];
    const float* cw4   = (const float*)d_in[7];
    const float* cb4   = (const float*)d_in[8];
    const float* cw5   = (const float*)d_in[9];
    const float* cb5   = (const float*)d_in[10];
    const float* fc1w  = (const float*)d_in[11];
    const float* fc1b  = (const float*)d_in[12];
    const float* fc2w  = (const float*)d_in[13];
    const float* fc2b  = (const float*)d_in[14];
    const float* emb   = (const float*)d_in[15];
    const float* Wall  = (const float*)d_in[16];
    float* out = (float*)d_out;

    float *c1, *c2, *c3, *c4, *c5;
    cudaGetSymbolAddress((void**)&c1, g_c1);
    cudaGetSymbolAddress((void**)&c2, g_c2);
    cudaGetSymbolAddress((void**)&c3, g_c3);
    cudaGetSymbolAddress((void**)&c4, g_c4);
    cudaGetSymbolAddress((void**)&c5, g_c5);

    // outputs/layer:          200704    100352     50176     25088     12544
    // OPT (=256/G):              256       128        64        32        16
    // blocks:                    784       784       784       784       784
    conv_split<3, 1,  true ><<<784, 256>>>(rgb, cw1, cb1, c1, 224, 224, 4, 112, 112);
    conv_split<4, 2,  true ><<<784, 256>>>(c1,  cw2, cb2, c2, 112, 112, 8,  56,  56);
    conv_split<8, 4,  true ><<<784, 256>>>(c2,  cw3, cb3, c3,  56,  56, 16, 28,  28);
    conv_split<16,8,  true ><<<784, 256>>>(c3,  cw4, cb4, c4,  28,  28, 32, 14,  14);
    conv_split<32,16, false><<<784, 256>>>(c4,  cw5, cb5, c5,  14,  14, 64,  7,   7);

    // head -> q, loss (loss lives at the last output element)
    head_k<<<1, 256>>>(c5, fc1w, fc1b, fc2w, fc2b, emb, out + (long long)out_size - 1);

    // big streaming GEMM: 2 float2 per thread
    const int TB = 256;
    long long nblocks = (NV + (long long)TB * 2 - 1) / ((long long)TB * 2);
    gemm_k<<<(unsigned)nblocks, TB>>>(Wall, out);
}

// round 4
// speedup vs baseline: 1.0631x; 1.0631x over previous
#include <cuda_runtime.h>

// ---------------- problem constants ----------------
#define B 4
#define T_TOTAL 35968706LL          // sum of all 52 weight-tensor sizes
#define NV (T_TOTAL / 2)            // float2 count per row (T is even)

// ---------------- device scratch (no allocs allowed) ----------------
__device__ float g_c1[4 * 4  * 112 * 112];
__device__ float g_c2[4 * 8  * 56  * 56];
__device__ float g_c3[4 * 16 * 28  * 28];
__device__ float g_c4[4 * 32 * 14  * 14];
__device__ float g_c5[4 * 64 * 7   * 7];
__device__ float g_q[64];           // q[b][j], b*16+j

// ---------------- split-K conv: k=4, s=2, p=1 ----------------
// Block = 256 threads = OPT outputs x G partial channel-groups.
// Output counts all divide OPT exactly, so no bounds guard on outputs.
template<int CIN, int G, bool LRELU>
__global__ void __launch_bounds__(256)
conv_split(const float* __restrict__ x, const float* __restrict__ w,
           const float* __restrict__ bias, float* __restrict__ y,
           int Hin, int Win, int Cout, int Hout, int Wout)
{
    constexpr int OPT = 256 / G;      // outputs per block
    constexpr int CPG = CIN / G;      // channels per partial group
    const int tid = threadIdx.x;
    const int g   = tid / OPT;
    const int ol  = tid % OPT;

    long long oidx = (long long)blockIdx.x * OPT + ol;
    int ow = (int)(oidx % Wout); long long t = oidx / Wout;
    int oh = (int)(t % Hout);    t /= Hout;
    int co = (int)(t % Cout);
    int n  = (int)(t / Cout);

    const int ih0 = oh * 2 - 1, iw0 = ow * 2 - 1;
    const float* xn = x + ((long long)n * CIN + g * CPG) * Hin * Win;
    const float* wc = w + ((long long)co * CIN + g * CPG) * 16;

    float acc = 0.f;
    #pragma unroll
    for (int ci = 0; ci < CPG; ci++) {
        const float* xc = xn + ci * Hin * Win;
        const float* wk = wc + ci * 16;
        #pragma unroll
        for (int kh = 0; kh < 4; kh++) {
            int ih = ih0 + kh;
            if ((unsigned)ih >= (unsigned)Hin) continue;
            const float* xr = xc + ih * Win;
            #pragma unroll
            for (int kw = 0; kw < 4; kw++) {
                int iw = iw0 + kw;
                if ((unsigned)iw < (unsigned)Win)
                    acc = fmaf(xr[iw], wk[kh * 4 + kw], acc);
            }
        }
    }

    if (G == 1) {
        acc += bias[co];
        if (LRELU) acc = (acc >= 0.f) ? acc : 0.01f * acc;
        y[oidx] = acc;
    } else {
        __shared__ float s[256];
        s[tid] = acc;
        __syncthreads();
        if (g == 0) {
            float sum = acc;
            #pragma unroll
            for (int j = 1; j < G; j++) sum += s[j * OPT + ol];
            sum += bias[co];
            if (LRELU) sum = (sum >= 0.f) ? sum : 0.01f * sum;
            y[oidx] = sum;
        }
    }
}

// ---------------- head: pool -> fc1 -> fc2 -> VQ -> q, loss ----------------
__global__ void head_k(const float* __restrict__ conv5,
                       const float* __restrict__ fc1w, const float* __restrict__ fc1b,
                       const float* __restrict__ fc2w, const float* __restrict__ fc2b,
                       const float* __restrict__ emb,
                       float* __restrict__ loss_out)
{
    __shared__ float sx[4][64];
    __shared__ float sh[4][16];
    __shared__ float se[4][16];
    __shared__ int   sidx[4];
    __shared__ float sred[64];
    int tid = threadIdx.x;                 // blockDim.x == 256

    // adaptive avg pool over 7x7
    {
        int b = tid >> 6, c = tid & 63;
        const float* p = conv5 + (b * 64 + c) * 49;
        float s = 0.f;
        #pragma unroll
        for (int i = 0; i < 49; i++) s += p[i];
        sx[b][c] = s * (1.f / 49.f);
    }
    __syncthreads();

    // fc1 (64->16) + lrelu
    if (tid < 64) {
        int b = tid >> 4, j = tid & 15;
        float s = fc1b[j];
        #pragma unroll
        for (int k = 0; k < 64; k++) s += sx[b][k] * fc1w[j * 64 + k];
        sh[b][j] = (s >= 0.f) ? s : 0.01f * s;
    }
    __syncthreads();

    // fc2 (16->16)
    if (tid < 64) {
        int b = tid >> 4, j = tid & 15;
        float s = fc2b[j];
        #pragma unroll
        for (int k = 0; k < 16; k++) s += sh[b][k] * fc2w[j * 16 + k];
        se[b][j] = s;
    }
    __syncthreads();

    // VQ nearest-codebook (first-min semantics like jnp.argmin)
    if (tid < 4) {
        int b = tid;
        float ee = 0.f;
        #pragma unroll
        for (int j = 0; j < 16; j++) ee += se[b][j] * se[b][j];
        float best = __int_as_float(0x7f800000);   // +inf
        int bi = 0;
        for (int c = 0; c < 4; c++) {
            float s2 = 0.f, dot = 0.f;
            #pragma unroll
            for (int j = 0; j < 16; j++) {
                float w = emb[c * 16 + j];
                s2  += w * w;
                dot += w * se[b][j];
            }
            float d = ee + s2 - 2.f * dot;
            if (d < best) { best = d; bi = c; }
        }
        sidx[b] = bi;
    }
    __syncthreads();

    // q + loss = 1.25 * mean((q - e)^2)
    if (tid < 64) {
        int b = tid >> 4, j = tid & 15;
        float qv = emb[sidx[b] * 16 + j];
        g_q[tid] = qv;
        float diff = qv - se[b][j];
        sred[tid] = diff * diff;
    }
    __syncthreads();
    if (tid == 0) {
        float s = 0.f;
        for (int i = 0; i < 64; i++) s += sred[i];
        *loss_out = 1.25f * s * (1.f / 64.f);
    }
}

// ---------------- the big streaming GEMM: out = q @ W_all ----------------
// One lane-contiguous float2 per thread: every LDG.64 across a warp covers
// exactly 256B contiguous -> fully coalesced. 16 independent loads/thread.
__global__ void __launch_bounds__(256)
gemm_k(const float* __restrict__ W, float* __restrict__ out)
{
    __shared__ float sq[64];
    if (threadIdx.x < 64) sq[threadIdx.x] = g_q[threadIdx.x];
    __syncthreads();

    long long i = (long long)blockIdx.x * blockDim.x + threadIdx.x;
    if (i >= NV) return;

    const float2* __restrict__ W2 = (const float2*)W;
    float2 a0 = {0.f, 0.f}, a1 = {0.f, 0.f}, a2 = {0.f, 0.f}, a3 = {0.f, 0.f};

    #pragma unroll
    for (int k = 0; k < 16; k++) {
        float2 w = __ldcs(&W2[(long long)k * NV + i]);
        float q0 = sq[k], q1 = sq[16 + k], q2 = sq[32 + k], q3 = sq[48 + k];
        a0.x = fmaf(q0, w.x, a0.x); a0.y = fmaf(q0, w.y, a0.y);
        a1.x = fmaf(q1, w.x, a1.x); a1.y = fmaf(q1, w.y, a1.y);
        a2.x = fmaf(q2, w.x, a2.x); a2.y = fmaf(q2, w.y, a2.y);
        a3.x = fmaf(q3, w.x, a3.x); a3.y = fmaf(q3, w.y, a3.y);
    }

    float2* __restrict__ O2 = (float2*)out;
    __stcs(&O2[i],          a0);
    __stcs(&O2[NV + i],     a1);
    __stcs(&O2[2 * NV + i], a2);
    __stcs(&O2[3 * NV + i], a3);
}

// ---------------- launch ----------------
extern "C" void kernel_launch(void* const* d_in, const int* in_sizes, int n_in,
                              void* d_out, int out_size)
{
    const float* rgb   = (const float*)d_in[0];
    const float* cw1   = (const float*)d_in[1];
    const float* cb1   = (const float*)d_in[2];
    const float* cw2   = (const float*)d_in[3];
    const float* cb2   = (const float*)d_in[4];
    const float* cw3   = (const float*)d_in[5];
    const float* cb3   = (const float*)d_in[6];
    const float* cw4   = (const float*)d_in[7];
    const float* cb4   = (const float*)d_in[8];
    const float* cw5   = (const float*)d_in[9];
    const float* cb5   = (const float*)d_in[10];
    const float* fc1w  = (const float*)d_in[11];
    const float* fc1b  = (const float*)d_in[12];
    const float* fc2w  = (const float*)d_in[13];
    const float* fc2b  = (const float*)d_in[14];
    const float* emb   = (const float*)d_in[15];
    const float* Wall  = (const float*)d_in[16];
    float* out = (float*)d_out;

    float *c1, *c2, *c3, *c4, *c5;
    cudaGetSymbolAddress((void**)&c1, g_c1);
    cudaGetSymbolAddress((void**)&c2, g_c2);
    cudaGetSymbolAddress((void**)&c3, g_c3);
    cudaGetSymbolAddress((void**)&c4, g_c4);
    cudaGetSymbolAddress((void**)&c5, g_c5);

    // outputs/layer:          200704    100352     50176     25088     12544
    // OPT (=256/G):              256       128        64        32        16
    // blocks:                    784       784       784       784       784
    conv_split<3, 1,  true ><<<784, 256>>>(rgb, cw1, cb1, c1, 224, 224, 4, 112, 112);
    conv_split<4, 2,  true ><<<784, 256>>>(c1,  cw2, cb2, c2, 112, 112, 8,  56,  56);
    conv_split<8, 4,  true ><<<784, 256>>>(c2,  cw3, cb3, c3,  56,  56, 16, 28,  28);
    conv_split<16,8,  true ><<<784, 256>>>(c3,  cw4, cb4, c4,  28,  28, 32, 14,  14);
    conv_split<32,16, false><<<784, 256>>>(c4,  cw5, cb5, c5,  14,  14, 64,  7,   7);

    // head -> q, loss (loss lives at the last output element)
    head_k<<<1, 256>>>(c5, fc1w, fc1b, fc2w, fc2b, emb, out + (long long)out_size - 1);

    // big streaming GEMM: one float2 per thread
    const int TB = 256;
    long long nblocks = (NV + TB - 1) / TB;
    gemm_k<<<(unsigned)nblocks, TB>>>(Wall, out);
}